// round 10
// baseline (speedup 1.0000x reference)
#include <cuda_runtime.h>
#include <math.h>

// Problem dims (fixed by the dataset)
#define BB   8
#define CC   18
#define NHYP 1024
#define KK   9
#define HW   65536
#define HW4  16384             // pixel quads per image
#define NPIX4 (BB*HW4)         // 131072 pixel quads per side

// Fused grid layout (round-5 proven best)
#define NSC   144              // scores blocks (2 sides * 8 b * 9 k)
#define SEGB  128              // seg blocks per side (1024 quads each)
#define SVOTB 512              // vote blocks per side (256 quads x 18 channels)
#define NSEG  (2*SEGB)
#define NVOT  (2*SVOTB)
#define NBLK  (NSC + NSEG + NVOT)

struct U2 { unsigned a, b; };

__device__ __forceinline__ U2 threefry2x32(unsigned k0, unsigned k1,
                                           unsigned x0, unsigned x1) {
    unsigned ks2 = 0x1BD11BDAu ^ k0 ^ k1;
    unsigned ks[3] = {k0, k1, ks2};
    const unsigned rot[8] = {13u,15u,26u,6u,17u,29u,16u,24u};
    x0 += ks[0]; x1 += ks[1];
#pragma unroll
    for (int d = 0; d < 5; ++d) {
#pragma unroll
        for (int r = 0; r < 4; ++r) {
            unsigned rr = rot[(d & 1) * 4 + r];
            x0 += x1;
            x1 = (x1 << rr) | (x1 >> (32u - rr));
            x1 ^= x0;
        }
        x0 += ks[(d + 1) % 3];
        x1 += ks[(d + 2) % 3] + (unsigned)(d + 1);
    }
    return U2{x0, x1};
}

// Scratch (allocation-free requirement -> device globals).
// Every slot is written on every call -> no zeroing kernel needed.
__device__ double   g_pvote[2][SVOTB];
__device__ double   g_pseg[2][SEGB];
__device__ double   g_pws[2][SEGB];
__device__ float    g_kp[2][72];
__device__ float    g_ent[2][72];
__device__ float    g_y[2][72];
__device__ unsigned g_count;   // zero-init; reset to 0 by the last block each call

__device__ __forceinline__ void l2_prefetch(const void* p) {
    asm volatile("prefetch.global.L2 [%0];" :: "l"(p));
}

__device__ __forceinline__ double blockReduceD(double v, double* sh) {
    int lane = threadIdx.x & 31, wid = threadIdx.x >> 5;
#pragma unroll
    for (int o = 16; o; o >>= 1) v += __shfl_down_sync(0xffffffffu, v, o);
    if (lane == 0) sh[wid] = v;
    __syncthreads();
    double r = 0.0;
    if (threadIdx.x < (blockDim.x >> 5)) r = sh[threadIdx.x];
    if (wid == 0) {
#pragma unroll
        for (int o = 16; o; o >>= 1) r += __shfl_down_sync(0xffffffffu, r, o);
    }
    __syncthreads();
    return r;  // valid on thread 0
}

__device__ __forceinline__ float nll1(float s0, float s1, int m) {
    float mx  = fmaxf(s0, s1);
    float lse = mx + log1pf(expf(-fabsf(s0 - s1)));
    return lse - (m ? s1 : s0);
}

__device__ __forceinline__ float sml1(float p, float q, float mf) {
    float d = fabsf(p - q) * mf;              // mf in {0,1}: branch-free masking
    return (d < 1.f) ? 0.5f * d * d : d - 0.5f;
}

// ---------------- scores part: per-(side,b,k) softmax/entropy/argmax ---------
__device__ void scores_part(
    int blk,
    const float* __restrict__ scL, const float* __restrict__ kpL,
    const float* __restrict__ qL,  const float* __restrict__ offL,
    const float* __restrict__ scR, const float* __restrict__ kpR,
    const float* __restrict__ qR,  const float* __restrict__ offR,
    const float* __restrict__ a_ptr) {
    __shared__ double shd[32];
    __shared__ float  shf[32];
    __shared__ int    shi[32];
    __shared__ float  s_max;
    __shared__ double sZ, sS1, sD;

    const int side = blk / 72;
    const int bk   = blk % 72;
    const int b = bk / KK, k = bk % KK;
    const float* sc  = side ? scR  : scL;
    const float* kp  = side ? kpR  : kpL;
    const float* qq  = side ? qR   : qL;
    const float* off = side ? offR : offL;
    const float a = *a_ptr;

    // jax.random.split(jax.random.key(1234)) -- partitionable threefry
    U2 kk = threefry2x32(0u, 1234u, 0u, (unsigned)side);
    const unsigned key0 = kk.a, key1 = kk.b;

    const float qx = qq[(b*KK + k)*2 + 0];
    const float qy = qq[(b*KK + k)*2 + 1];

    float sp[4], dist[4];
    float mx = -INFINITY, zbest = -INFINITY;
    int ibest = NHYP;
#pragma unroll
    for (int j = 0; j < 4; ++j) {
        int n   = threadIdx.x + j * 256;
        int idx = (b * NHYP + n) * KK + k;
        float s = a * sc[idx];
        sp[j] = s;
        mx = fmaxf(mx, s);
        float dx = kp[2*idx]   - qx;
        float dy = kp[2*idx+1] - qy;
        dist[j] = sqrtf(dx*dx + dy*dy);

        unsigned fj = (unsigned)(b * (NHYP*KK) + n * KK + k);
        U2 r = threefry2x32(key0, key1, 0u, fj);
        unsigned bits = r.a ^ r.b;
        float f = __uint_as_float(0x3f800000u | (bits >> 9)) - 1.0f;
        if (f == 0.0f) f = 1.17549435e-38f;
        float g = -logf(-logf(f));
        float z = g + s;
        if (z > zbest) { zbest = z; ibest = n; }
    }

    // block max
    {
        int lane = threadIdx.x & 31, wid = threadIdx.x >> 5;
#pragma unroll
        for (int o = 16; o; o >>= 1) mx = fmaxf(mx, __shfl_down_sync(0xffffffffu, mx, o));
        if (lane == 0) shf[wid] = mx;
        __syncthreads();
        if (threadIdx.x == 0) {
            float m2 = shf[0];
            for (int i = 1; i < 8; ++i) m2 = fmaxf(m2, shf[i]);
            s_max = m2;
        }
        __syncthreads();
        mx = s_max;
    }

    float Z = 0.f, S1 = 0.f, D = 0.f;
#pragma unroll
    for (int j = 0; j < 4; ++j) {
        float e = expf(sp[j] - mx);
        Z += e; S1 += e * (sp[j] - mx); D += e * dist[j];
    }
    double Zt  = blockReduceD((double)Z,  shd); if (threadIdx.x == 0) sZ  = Zt;
    double S1t = blockReduceD((double)S1, shd); if (threadIdx.x == 0) sS1 = S1t;
    double Dt  = blockReduceD((double)D,  shd); if (threadIdx.x == 0) sD  = Dt;

    // argmax reduce (first index wins on ties)
    {
        int lane = threadIdx.x & 31, wid = threadIdx.x >> 5;
#pragma unroll
        for (int o = 16; o; o >>= 1) {
            float oz = __shfl_down_sync(0xffffffffu, zbest, o);
            int   oi = __shfl_down_sync(0xffffffffu, ibest, o);
            if (oz > zbest || (oz == zbest && oi < ibest)) { zbest = oz; ibest = oi; }
        }
        if (lane == 0) { shf[wid] = zbest; shi[wid] = ibest; }
        __syncthreads();
        if (threadIdx.x == 0) {
            for (int i = 1; i < 8; ++i)
                if (shf[i] > zbest || (shf[i] == zbest && shi[i] < ibest)) {
                    zbest = shf[i]; ibest = shi[i];
                }
            double Zv = sZ;
            g_kp[side][bk]  = (float)(sD / Zv);
            g_ent[side][bk] = (float)((log(Zv) - sS1 / Zv) * 1.4426950408889634);
            g_y[side][bk]   = kp[((b * NHYP + ibest) * KK + k) * 2 + 1] + off[b * 2 + 1];
        }
    }
}

// ---------------- seg part: contiguous chunks + early L2 prefetch -------------
__device__ void seg_part(
    int blk,
    const float* __restrict__ sL, const int* __restrict__ mL,
    const float* __restrict__ sR, const int* __restrict__ mR) {
    __shared__ double sh[32];
    const int side = blk & 1;
    const int sb   = blk >> 1;                  // 0..127
    const int b    = sb >> 4;                   // 16 blocks per batch image
    const int qb   = (sb & 15) * 1024;          // contiguous 1024-quad chunk
    const float4* s0 = (const float4*)(side ? sR : sL) + b * 2 * HW4 + qb;
    const float4* s1 = s0 + HW4;
    const int4*   m4 = (const int4*)(side ? mR : mL) + b * HW4 + qb;
    const bool pf = ((threadIdx.x & 7) == 0);   // one lane per 128B line
    float acc = 0.f; int wcnt = 0;
#pragma unroll
    for (int it = 0; it < 4; ++it) {
        int q = it * 256 + threadIdx.x;
        float4 a0 = __ldcs(s0 + q);
        float4 a1 = __ldcs(s1 + q);
        int4 m = m4[q];
        if (it == 0 && pf) {
#pragma unroll
            for (int jt = 1; jt < 4; ++jt) {
                int qp = jt * 256 + threadIdx.x;
                l2_prefetch(s0 + qp);
                l2_prefetch(s1 + qp);
                l2_prefetch(m4 + qp);
            }
        }
        acc += nll1(a0.x, a1.x, m.x) + nll1(a0.y, a1.y, m.y)
             + nll1(a0.z, a1.z, m.z) + nll1(a0.w, a1.w, m.w);
        wcnt += m.x + m.y + m.z + m.w;
    }
    double t = blockReduceD((double)acc, sh);
    if (threadIdx.x == 0) g_pseg[side][sb] = t;
    double w = blockReduceD((double)wcnt, sh);
    if (threadIdx.x == 0) g_pws[side][sb] = w;
}

// ---------------- vote part: R5 mapping + full-lead L2 prefetch ---------------
// Each block: 256 contiguous pixel quads of one batch image, all 18 channels.
// 12 front-batched 16B loads per group; mask loaded once per thread.
// ALL remaining groups (1 and 2) are prefetched into L2 immediately after
// group 0's loads issue -> group 1 gets ~1 group-latency lead, group 2 ~2.
__device__ void vote_part(
    int blk,
    const float* __restrict__ pL, const float* __restrict__ gL, const int* __restrict__ mL,
    const float* __restrict__ pR, const float* __restrict__ gR, const int* __restrict__ mR) {
    __shared__ double sh[32];
    const int side = blk & 1;
    const int vb   = blk >> 1;                  // 0..511
    const int b    = vb >> 6;                   // 64 blocks per batch image
    const int pix4 = (vb & 63) * 256 + threadIdx.x;
    const int4 m   = ((const int4*)(side ? mR : mL))[b * HW4 + pix4];
    const float mfx = (float)m.x, mfy = (float)m.y, mfz = (float)m.z, mfw = (float)m.w;

    const float4* p4 = (const float4*)(side ? pR : pL) + b * CC * HW4 + pix4;
    const float4* q4 = (const float4*)(side ? gR : gL) + b * CC * HW4 + pix4;
    const bool pf = ((threadIdx.x & 7) == 0);   // one lane per 128B line

    float ax = 0.f, ay = 0.f, az = 0.f, aw = 0.f;
#pragma unroll
    for (int g = 0; g < 3; ++g) {
        float4 P[6], Q[6];
#pragma unroll
        for (int j = 0; j < 6; ++j) {
            int c = g * 6 + j;
            P[j] = __ldcs(p4 + c * HW4);
        }
#pragma unroll
        for (int j = 0; j < 6; ++j) {
            int c = g * 6 + j;
            Q[j] = __ldcs(q4 + c * HW4);
        }
        // after group 0's loads: prefetch EVERYTHING remaining (groups 1 and 2)
        if (g == 0 && pf) {
#pragma unroll
            for (int c = 6; c < CC; ++c) {
                l2_prefetch(p4 + c * HW4);
                l2_prefetch(q4 + c * HW4);
            }
        }
#pragma unroll
        for (int j = 0; j < 6; ++j) {
            ax += sml1(P[j].x, Q[j].x, mfx);
            ay += sml1(P[j].y, Q[j].y, mfy);
            az += sml1(P[j].z, Q[j].z, mfz);
            aw += sml1(P[j].w, Q[j].w, mfw);
        }
    }
    float acc = (ax + ay) + (az + aw);
    double t = blockReduceD((double)acc, sh);
    if (threadIdx.x == 0) g_pvote[side][vb] = t;
}

// ---------------- final scalar combine (runs in last finishing block) ---------
__device__ void final_combine(const int* __restrict__ epoch_ptr,
                              float* __restrict__ out) {
    __shared__ double shd[32];
    __shared__ float sh_kp[144];
    __shared__ float sh_y[144];
    __shared__ float sh_entb[16];
    __shared__ double s_vote[2], s_seg[2], s_ws[2];
    int t = threadIdx.x;
    if (t < 144) {
        int side = t / 72, bk = t % 72;
        sh_kp[t] = g_kp[side][bk];
        sh_y[t]  = g_y[side][bk];
    }
    if (t < 16) {
        int side = t >> 3, b = t & 7;
        float s = 0.f;
        for (int k = 0; k < KK; ++k) s += g_ent[side][b * KK + k];
        sh_entb[t] = fabsf(s / 9.f - 6.f);
    }
    __syncthreads();

    for (int side = 0; side < 2; ++side) {
        double v = 0.0;
        for (int j = t; j < SVOTB; j += 256) v += g_pvote[side][j];
        double r = blockReduceD(v, shd);
        if (t == 0) s_vote[side] = r;

        double sg = (t < SEGB) ? g_pseg[side][t] : 0.0;
        r = blockReduceD(sg, shd);
        if (t == 0) s_seg[side] = r;

        double w = (t < SEGB) ? g_pws[side][t] : 0.0;
        r = blockReduceD(w, shd);
        if (t == 0) s_ws[side] = r;
    }
    __syncthreads();

    if (t == 0) {
        double kpS0 = 0, kpS1 = 0, epi = 0;
        for (int i = 0; i < 72; ++i) {
            kpS0 += sh_kp[i]; kpS1 += sh_kp[72 + i];
            float d = fabsf(sh_y[i] - sh_y[72 + i]);
            if (!isfinite(d)) d = 0.f;
            epi += d;
        }
        double entS0 = 0, entS1 = 0;
        for (int i = 0; i < 8; ++i) { entS0 += sh_entb[i]; entS1 += sh_entb[8 + i]; }

        double kp_loss  = (kpS0 / 72.0 + kpS1 / 72.0) * 0.5;
        double ent_loss = (entS0 / 8.0 + entS1 / 8.0) * 0.5;

        double voteS[2];
        for (int s2 = 0; s2 < 2; ++s2) {
            double v = s_vote[s2], w = s_ws[s2];
            voteS[s2] = (w > 0.0) ? v / fmax(w, 1.0) / (double)CC : v;
        }
        double vote_loss = (voteS[0] + voteS[1]) * 0.5;
        double seg_loss  = (s_seg[0] + s_seg[1]) * 0.5 / (double)(BB * HW);

        double kp_w   = 1.0 / (1.0 + exp(-0.5 * (20.0 - kp_loss)));
        double vote_w = 1.0 - kp_w;
        double epim   = epi / 72.0;
        int epoch = *epoch_ptr;
        double vertex = (epoch > 49)
            ? kp_w * (kp_loss + epim) + vote_w * vote_loss
            : kp_w * kp_loss + vote_w * vote_loss;
        out[0] = (float)(vertex + ent_loss + seg_loss);
    }
}

// ---------------- single fused kernel ------------------------------------------
__global__ void __launch_bounds__(256) mega_kernel(
    const float* __restrict__ vpL, const float* __restrict__ vgL, const int* __restrict__ mkL,
    const float* __restrict__ sgL, const float* __restrict__ kpL, const float* __restrict__ scL,
    const float* __restrict__ qL,  const float* __restrict__ ofL,
    const float* __restrict__ vpR, const float* __restrict__ vgR, const int* __restrict__ mkR,
    const float* __restrict__ sgR, const float* __restrict__ kpR, const float* __restrict__ scR,
    const float* __restrict__ qR,  const float* __restrict__ ofR,
    const float* __restrict__ a_ptr, const int* __restrict__ epoch_ptr,
    float* __restrict__ out) {
    int blk = blockIdx.x;
    if (blk < NSC) {
        scores_part(blk, scL, kpL, qL, ofL, scR, kpR, qR, ofR, a_ptr);
    } else if (blk < NSC + NSEG) {
        seg_part(blk - NSC, sgL, mkL, sgR, mkR);
    } else {
        vote_part(blk - NSC - NSEG, vpL, vgL, mkL, vpR, vgR, mkR);
    }

    // last-block grid reduction
    __shared__ unsigned s_last;
    __syncthreads();
    if (threadIdx.x == 0) {
        __threadfence();                        // make this block's partials visible
        s_last = (atomicAdd(&g_count, 1u) == (unsigned)(NBLK - 1));
    }
    __syncthreads();
    if (s_last) {
        if (threadIdx.x == 0) g_count = 0;      // reset for next graph replay
        __threadfence_block();
        final_combine(epoch_ptr, out);
    }
}

extern "C" void kernel_launch(void* const* d_in, const int* in_sizes, int n_in,
                              void* d_out, int out_size) {
    const float* vpL = (const float*)d_in[0];
    const float* vgL = (const float*)d_in[1];
    const int*   mkL = (const int*)  d_in[2];
    const float* sgL = (const float*)d_in[3];
    const float* kpL = (const float*)d_in[4];
    const float* scL = (const float*)d_in[5];
    const float* qL  = (const float*)d_in[6];
    const float* ofL = (const float*)d_in[7];
    const float* vpR = (const float*)d_in[8];
    const float* vgR = (const float*)d_in[9];
    const int*   mkR = (const int*)  d_in[10];
    const float* sgR = (const float*)d_in[11];
    const float* kpR = (const float*)d_in[12];
    const float* scR = (const float*)d_in[13];
    const float* qR  = (const float*)d_in[14];
    const float* ofR = (const float*)d_in[15];
    const float* a   = (const float*)d_in[16];
    const int*   ep  = (const int*)  d_in[17];
    float* out = (float*)d_out;

    mega_kernel<<<NBLK, 256>>>(vpL, vgL, mkL, sgL, kpL, scL, qL, ofL,
                               vpR, vgR, mkR, sgR, kpR, scR, qR, ofR,
                               a, ep, out);
}

// round 11
// speedup vs baseline: 1.1322x; 1.1322x over previous
#include <cuda_runtime.h>
#include <math.h>

// Problem dims (fixed by the dataset)
#define BB   8
#define CC   18
#define NHYP 1024
#define KK   9
#define HW   65536
#define HW4  16384             // pixel quads per image
#define NPIX4 (BB*HW4)         // 131072 pixel quads per side

// Fused grid layout (round-5 proven best)
#define NSC   144              // scores blocks (2 sides * 8 b * 9 k)
#define SEGB  128              // seg blocks per side (1024 quads each)
#define SVOTB 512              // vote blocks per side (256 quads x 18 channels)
#define NSEG  (2*SEGB)
#define NVOT  (2*SVOTB)
#define NBLK  (NSC + NSEG + NVOT)

struct U2 { unsigned a, b; };

__device__ __forceinline__ U2 threefry2x32(unsigned k0, unsigned k1,
                                           unsigned x0, unsigned x1) {
    unsigned ks2 = 0x1BD11BDAu ^ k0 ^ k1;
    unsigned ks[3] = {k0, k1, ks2};
    const unsigned rot[8] = {13u,15u,26u,6u,17u,29u,16u,24u};
    x0 += ks[0]; x1 += ks[1];
#pragma unroll
    for (int d = 0; d < 5; ++d) {
#pragma unroll
        for (int r = 0; r < 4; ++r) {
            unsigned rr = rot[(d & 1) * 4 + r];
            x0 += x1;
            x1 = (x1 << rr) | (x1 >> (32u - rr));
            x1 ^= x0;
        }
        x0 += ks[(d + 1) % 3];
        x1 += ks[(d + 2) % 3] + (unsigned)(d + 1);
    }
    return U2{x0, x1};
}

// Scratch (allocation-free requirement -> device globals).
// Every slot is written on every call -> no zeroing kernel needed.
__device__ double   g_pvote[2][SVOTB];
__device__ double   g_pseg[2][SEGB];
__device__ double   g_pws[2][SEGB];
__device__ float    g_kp[2][72];
__device__ float    g_ent[2][72];
__device__ float    g_y[2][72];
__device__ unsigned g_count;   // zero-init; reset to 0 by the last block each call

__device__ __forceinline__ void l2_prefetch(const void* p) {
    asm volatile("prefetch.global.L2 [%0];" :: "l"(p));
}

__device__ __forceinline__ double blockReduceD(double v, double* sh) {
    int lane = threadIdx.x & 31, wid = threadIdx.x >> 5;
#pragma unroll
    for (int o = 16; o; o >>= 1) v += __shfl_down_sync(0xffffffffu, v, o);
    if (lane == 0) sh[wid] = v;
    __syncthreads();
    double r = 0.0;
    if (threadIdx.x < (blockDim.x >> 5)) r = sh[threadIdx.x];
    if (wid == 0) {
#pragma unroll
        for (int o = 16; o; o >>= 1) r += __shfl_down_sync(0xffffffffu, r, o);
    }
    __syncthreads();
    return r;  // valid on thread 0
}

__device__ __forceinline__ float nll1(float s0, float s1, int m) {
    float mx  = fmaxf(s0, s1);
    float lse = mx + log1pf(expf(-fabsf(s0 - s1)));
    return lse - (m ? s1 : s0);
}

__device__ __forceinline__ float sml1(float p, float q, float mf) {
    float d = fabsf(p - q) * mf;              // mf in {0,1}: branch-free masking
    return (d < 1.f) ? 0.5f * d * d : d - 0.5f;
}

// ---------------- scores part: per-(side,b,k) softmax/entropy/argmax ---------
__device__ void scores_part(
    int blk,
    const float* __restrict__ scL, const float* __restrict__ kpL,
    const float* __restrict__ qL,  const float* __restrict__ offL,
    const float* __restrict__ scR, const float* __restrict__ kpR,
    const float* __restrict__ qR,  const float* __restrict__ offR,
    const float* __restrict__ a_ptr) {
    __shared__ double shd[32];
    __shared__ float  shf[32];
    __shared__ int    shi[32];
    __shared__ float  s_max;
    __shared__ double sZ, sS1, sD;

    const int side = blk / 72;
    const int bk   = blk % 72;
    const int b = bk / KK, k = bk % KK;
    const float* sc  = side ? scR  : scL;
    const float* kp  = side ? kpR  : kpL;
    const float* qq  = side ? qR   : qL;
    const float* off = side ? offR : offL;
    const float a = *a_ptr;

    // jax.random.split(jax.random.key(1234)) -- partitionable threefry
    U2 kk = threefry2x32(0u, 1234u, 0u, (unsigned)side);
    const unsigned key0 = kk.a, key1 = kk.b;

    const float qx = qq[(b*KK + k)*2 + 0];
    const float qy = qq[(b*KK + k)*2 + 1];

    float sp[4], dist[4];
    float mx = -INFINITY, zbest = -INFINITY;
    int ibest = NHYP;
#pragma unroll
    for (int j = 0; j < 4; ++j) {
        int n   = threadIdx.x + j * 256;
        int idx = (b * NHYP + n) * KK + k;
        float s = a * sc[idx];
        sp[j] = s;
        mx = fmaxf(mx, s);
        float dx = kp[2*idx]   - qx;
        float dy = kp[2*idx+1] - qy;
        dist[j] = sqrtf(dx*dx + dy*dy);

        unsigned fj = (unsigned)(b * (NHYP*KK) + n * KK + k);
        U2 r = threefry2x32(key0, key1, 0u, fj);
        unsigned bits = r.a ^ r.b;
        float f = __uint_as_float(0x3f800000u | (bits >> 9)) - 1.0f;
        if (f == 0.0f) f = 1.17549435e-38f;
        float g = -logf(-logf(f));
        float z = g + s;
        if (z > zbest) { zbest = z; ibest = n; }
    }

    // block max
    {
        int lane = threadIdx.x & 31, wid = threadIdx.x >> 5;
#pragma unroll
        for (int o = 16; o; o >>= 1) mx = fmaxf(mx, __shfl_down_sync(0xffffffffu, mx, o));
        if (lane == 0) shf[wid] = mx;
        __syncthreads();
        if (threadIdx.x == 0) {
            float m2 = shf[0];
            for (int i = 1; i < 8; ++i) m2 = fmaxf(m2, shf[i]);
            s_max = m2;
        }
        __syncthreads();
        mx = s_max;
    }

    float Z = 0.f, S1 = 0.f, D = 0.f;
#pragma unroll
    for (int j = 0; j < 4; ++j) {
        float e = expf(sp[j] - mx);
        Z += e; S1 += e * (sp[j] - mx); D += e * dist[j];
    }
    double Zt  = blockReduceD((double)Z,  shd); if (threadIdx.x == 0) sZ  = Zt;
    double S1t = blockReduceD((double)S1, shd); if (threadIdx.x == 0) sS1 = S1t;
    double Dt  = blockReduceD((double)D,  shd); if (threadIdx.x == 0) sD  = Dt;

    // argmax reduce (first index wins on ties)
    {
        int lane = threadIdx.x & 31, wid = threadIdx.x >> 5;
#pragma unroll
        for (int o = 16; o; o >>= 1) {
            float oz = __shfl_down_sync(0xffffffffu, zbest, o);
            int   oi = __shfl_down_sync(0xffffffffu, ibest, o);
            if (oz > zbest || (oz == zbest && oi < ibest)) { zbest = oz; ibest = oi; }
        }
        if (lane == 0) { shf[wid] = zbest; shi[wid] = ibest; }
        __syncthreads();
        if (threadIdx.x == 0) {
            for (int i = 1; i < 8; ++i)
                if (shf[i] > zbest || (shf[i] == zbest && shi[i] < ibest)) {
                    zbest = shf[i]; ibest = shi[i];
                }
            double Zv = sZ;
            g_kp[side][bk]  = (float)(sD / Zv);
            g_ent[side][bk] = (float)((log(Zv) - sS1 / Zv) * 1.4426950408889634);
            g_y[side][bk]   = kp[((b * NHYP + ibest) * KK + k) * 2 + 1] + off[b * 2 + 1];
        }
    }
}

// ---------------- seg part: contiguous chunks + staggered L2 prefetch ---------
// During iteration it's loads, prefetch only iteration it+1's three lines
// (same staggered schedule that worked for vote; avoids R10's burst).
__device__ void seg_part(
    int blk,
    const float* __restrict__ sL, const int* __restrict__ mL,
    const float* __restrict__ sR, const int* __restrict__ mR) {
    __shared__ double sh[32];
    const int side = blk & 1;
    const int sb   = blk >> 1;                  // 0..127
    const int b    = sb >> 4;                   // 16 blocks per batch image
    const int qb   = (sb & 15) * 1024;          // contiguous 1024-quad chunk
    const float4* s0 = (const float4*)(side ? sR : sL) + b * 2 * HW4 + qb;
    const float4* s1 = s0 + HW4;
    const int4*   m4 = (const int4*)(side ? mR : mL) + b * HW4 + qb;
    const bool pf = ((threadIdx.x & 7) == 0);   // one lane per 128B line
    float acc = 0.f; int wcnt = 0;
#pragma unroll
    for (int it = 0; it < 4; ++it) {
        int q = it * 256 + threadIdx.x;
        float4 a0 = __ldcs(s0 + q);
        float4 a1 = __ldcs(s1 + q);
        int4 m = m4[q];
        if (it < 3 && pf) {
            int qp = (it + 1) * 256 + threadIdx.x;
            l2_prefetch(s0 + qp);
            l2_prefetch(s1 + qp);
            l2_prefetch(m4 + qp);
        }
        acc += nll1(a0.x, a1.x, m.x) + nll1(a0.y, a1.y, m.y)
             + nll1(a0.z, a1.z, m.z) + nll1(a0.w, a1.w, m.w);
        wcnt += m.x + m.y + m.z + m.w;
    }
    double t = blockReduceD((double)acc, sh);
    if (threadIdx.x == 0) g_pseg[side][sb] = t;
    double w = blockReduceD((double)wcnt, sh);
    if (threadIdx.x == 0) g_pws[side][sb] = w;
}

// ---------------- vote part: R9 winner (staggered next-group L2 prefetch) -----
// Each block: 256 contiguous pixel quads of one batch image, all 18 channels.
// 12 front-batched 16B loads per group; mask loaded once per thread.
// After issuing group g's loads, one lane per 128B line prefetches group g+1
// into L2 so its consumption sees L2-hit latency instead of DRAM latency.
__device__ void vote_part(
    int blk,
    const float* __restrict__ pL, const float* __restrict__ gL, const int* __restrict__ mL,
    const float* __restrict__ pR, const float* __restrict__ gR, const int* __restrict__ mR) {
    __shared__ double sh[32];
    const int side = blk & 1;
    const int vb   = blk >> 1;                  // 0..511
    const int b    = vb >> 6;                   // 64 blocks per batch image
    const int pix4 = (vb & 63) * 256 + threadIdx.x;
    const int4 m   = ((const int4*)(side ? mR : mL))[b * HW4 + pix4];
    const float mfx = (float)m.x, mfy = (float)m.y, mfz = (float)m.z, mfw = (float)m.w;

    const float4* p4 = (const float4*)(side ? pR : pL) + b * CC * HW4 + pix4;
    const float4* q4 = (const float4*)(side ? gR : gL) + b * CC * HW4 + pix4;
    const bool pf = ((threadIdx.x & 7) == 0);   // one lane per 128B line

    float ax = 0.f, ay = 0.f, az = 0.f, aw = 0.f;
#pragma unroll
    for (int g = 0; g < 3; ++g) {
        float4 P[6], Q[6];
#pragma unroll
        for (int j = 0; j < 6; ++j) {
            int c = g * 6 + j;
            P[j] = __ldcs(p4 + c * HW4);
        }
#pragma unroll
        for (int j = 0; j < 6; ++j) {
            int c = g * 6 + j;
            Q[j] = __ldcs(q4 + c * HW4);
        }
        // prefetch next group's lines into L2 while this group's loads fly
        if (g < 2 && pf) {
#pragma unroll
            for (int j = 0; j < 6; ++j) {
                int c = (g + 1) * 6 + j;
                l2_prefetch(p4 + c * HW4);
                l2_prefetch(q4 + c * HW4);
            }
        }
#pragma unroll
        for (int j = 0; j < 6; ++j) {
            ax += sml1(P[j].x, Q[j].x, mfx);
            ay += sml1(P[j].y, Q[j].y, mfy);
            az += sml1(P[j].z, Q[j].z, mfz);
            aw += sml1(P[j].w, Q[j].w, mfw);
        }
    }
    float acc = (ax + ay) + (az + aw);
    double t = blockReduceD((double)acc, sh);
    if (threadIdx.x == 0) g_pvote[side][vb] = t;
}

// ---------------- final scalar combine (runs in last finishing block) ---------
__device__ void final_combine(const int* __restrict__ epoch_ptr,
                              float* __restrict__ out) {
    __shared__ double shd[32];
    __shared__ float sh_kp[144];
    __shared__ float sh_y[144];
    __shared__ float sh_entb[16];
    __shared__ double s_vote[2], s_seg[2], s_ws[2];
    int t = threadIdx.x;
    if (t < 144) {
        int side = t / 72, bk = t % 72;
        sh_kp[t] = g_kp[side][bk];
        sh_y[t]  = g_y[side][bk];
    }
    if (t < 16) {
        int side = t >> 3, b = t & 7;
        float s = 0.f;
        for (int k = 0; k < KK; ++k) s += g_ent[side][b * KK + k];
        sh_entb[t] = fabsf(s / 9.f - 6.f);
    }
    __syncthreads();

    for (int side = 0; side < 2; ++side) {
        double v = 0.0;
        for (int j = t; j < SVOTB; j += 256) v += g_pvote[side][j];
        double r = blockReduceD(v, shd);
        if (t == 0) s_vote[side] = r;

        double sg = (t < SEGB) ? g_pseg[side][t] : 0.0;
        r = blockReduceD(sg, shd);
        if (t == 0) s_seg[side] = r;

        double w = (t < SEGB) ? g_pws[side][t] : 0.0;
        r = blockReduceD(w, shd);
        if (t == 0) s_ws[side] = r;
    }
    __syncthreads();

    if (t == 0) {
        double kpS0 = 0, kpS1 = 0, epi = 0;
        for (int i = 0; i < 72; ++i) {
            kpS0 += sh_kp[i]; kpS1 += sh_kp[72 + i];
            float d = fabsf(sh_y[i] - sh_y[72 + i]);
            if (!isfinite(d)) d = 0.f;
            epi += d;
        }
        double entS0 = 0, entS1 = 0;
        for (int i = 0; i < 8; ++i) { entS0 += sh_entb[i]; entS1 += sh_entb[8 + i]; }

        double kp_loss  = (kpS0 / 72.0 + kpS1 / 72.0) * 0.5;
        double ent_loss = (entS0 / 8.0 + entS1 / 8.0) * 0.5;

        double voteS[2];
        for (int s2 = 0; s2 < 2; ++s2) {
            double v = s_vote[s2], w = s_ws[s2];
            voteS[s2] = (w > 0.0) ? v / fmax(w, 1.0) / (double)CC : v;
        }
        double vote_loss = (voteS[0] + voteS[1]) * 0.5;
        double seg_loss  = (s_seg[0] + s_seg[1]) * 0.5 / (double)(BB * HW);

        double kp_w   = 1.0 / (1.0 + exp(-0.5 * (20.0 - kp_loss)));
        double vote_w = 1.0 - kp_w;
        double epim   = epi / 72.0;
        int epoch = *epoch_ptr;
        double vertex = (epoch > 49)
            ? kp_w * (kp_loss + epim) + vote_w * vote_loss
            : kp_w * kp_loss + vote_w * vote_loss;
        out[0] = (float)(vertex + ent_loss + seg_loss);
    }
}

// ---------------- single fused kernel ------------------------------------------
__global__ void __launch_bounds__(256) mega_kernel(
    const float* __restrict__ vpL, const float* __restrict__ vgL, const int* __restrict__ mkL,
    const float* __restrict__ sgL, const float* __restrict__ kpL, const float* __restrict__ scL,
    const float* __restrict__ qL,  const float* __restrict__ ofL,
    const float* __restrict__ vpR, const float* __restrict__ vgR, const int* __restrict__ mkR,
    const float* __restrict__ sgR, const float* __restrict__ kpR, const float* __restrict__ scR,
    const float* __restrict__ qR,  const float* __restrict__ ofR,
    const float* __restrict__ a_ptr, const int* __restrict__ epoch_ptr,
    float* __restrict__ out) {
    int blk = blockIdx.x;
    if (blk < NSC) {
        scores_part(blk, scL, kpL, qL, ofL, scR, kpR, qR, ofR, a_ptr);
    } else if (blk < NSC + NSEG) {
        seg_part(blk - NSC, sgL, mkL, sgR, mkR);
    } else {
        vote_part(blk - NSC - NSEG, vpL, vgL, mkL, vpR, vgR, mkR);
    }

    // last-block grid reduction
    __shared__ unsigned s_last;
    __syncthreads();
    if (threadIdx.x == 0) {
        __threadfence();                        // make this block's partials visible
        s_last = (atomicAdd(&g_count, 1u) == (unsigned)(NBLK - 1));
    }
    __syncthreads();
    if (s_last) {
        if (threadIdx.x == 0) g_count = 0;      // reset for next graph replay
        __threadfence_block();
        final_combine(epoch_ptr, out);
    }
}

extern "C" void kernel_launch(void* const* d_in, const int* in_sizes, int n_in,
                              void* d_out, int out_size) {
    const float* vpL = (const float*)d_in[0];
    const float* vgL = (const float*)d_in[1];
    const int*   mkL = (const int*)  d_in[2];
    const float* sgL = (const float*)d_in[3];
    const float* kpL = (const float*)d_in[4];
    const float* scL = (const float*)d_in[5];
    const float* qL  = (const float*)d_in[6];
    const float* ofL = (const float*)d_in[7];
    const float* vpR = (const float*)d_in[8];
    const float* vgR = (const float*)d_in[9];
    const int*   mkR = (const int*)  d_in[10];
    const float* sgR = (const float*)d_in[11];
    const float* kpR = (const float*)d_in[12];
    const float* scR = (const float*)d_in[13];
    const float* qR  = (const float*)d_in[14];
    const float* ofR = (const float*)d_in[15];
    const float* a   = (const float*)d_in[16];
    const int*   ep  = (const int*)  d_in[17];
    float* out = (float*)d_out;

    mega_kernel<<<NBLK, 256>>>(vpL, vgL, mkL, sgL, kpL, scL, qL, ofL,
                               vpR, vgR, mkR, sgR, kpR, scR, qR, ofR,
                               a, ep, out);
}